// round 7
// baseline (speedup 1.0000x reference)
#include <cuda_runtime.h>
#include <cuda_fp16.h>
#include <math.h>
#include <stdint.h>

// Problem constants (fixed shapes)
constexpr int Bb  = 2;
constexpr int Lc  = 4096;
constexpr int Dc  = 2048;
constexpr int Hh  = 32;
constexpr int Kc  = 16;
constexpr int HDc = 64;
constexpr int NMBc = 256;           // L / K
constexpr int Mrows = Bb * Lc;      // 8192

// Scratch (device globals; allocation in kernel_launch is forbidden)
__device__ float g_q  [(size_t)Bb*Hh*NMBc*Kc*HDc];   // scan layout [b][h][n][k][d]
__device__ float g_k  [(size_t)Bb*Hh*NMBc*Kc*HDc];
__device__ float g_v  [(size_t)Bb*Hh*NMBc*Kc*HDc];
__device__ float g_eta[(size_t)Bb*Hh*NMBc*Kc];
__device__ float g_y  [(size_t)Bb*Lc*Dc];            // scan output, token layout

// fp16 operands for tensor-core GEMMs (A: hi only; W: hi/lo split)
__device__ __half g_ah [(size_t)Mrows*Dc];
__device__ __half g_wqh[(size_t)Dc*Dc];
__device__ __half g_wql[(size_t)Dc*Dc];
__device__ __half g_wkh[(size_t)Dc*Dc];
__device__ __half g_wkl[(size_t)Dc*Dc];
__device__ __half g_wvh[(size_t)Dc*Dc];
__device__ __half g_wvl[(size_t)Dc*Dc];
__device__ __half g_woh[(size_t)Dc*Dc];
__device__ __half g_wol[(size_t)Dc*Dc];
__device__ __half g_xnh[(size_t)Mrows*Dc];

__device__ __forceinline__ void cp16(uint32_t dst, const void* src) {
    asm volatile("cp.async.cg.shared.global [%0], [%1], 16;\n" :: "r"(dst), "l"(src));
}

// ---------------------------------------------------------------------------
// fp32 -> fp16 (hi only).  n multiple of 1024.
// ---------------------------------------------------------------------------
__global__ __launch_bounds__(256) void conv_hi_kernel(
    const float* __restrict__ x, __half* __restrict__ hi, int n)
{
    int i = (blockIdx.x*256 + threadIdx.x)*4;
    if (i >= n) return;
    float4 v = *(const float4*)&x[i];
    __half h[4];
    h[0] = __float2half_rn(v.x); h[1] = __float2half_rn(v.y);
    h[2] = __float2half_rn(v.z); h[3] = __float2half_rn(v.w);
    *(uint2*)&hi[i] = *(uint2*)h;
}

// ---------------------------------------------------------------------------
// fp32 -> fp16 (hi, lo) split.  n multiple of 1024.
// ---------------------------------------------------------------------------
__global__ __launch_bounds__(256) void conv_hilo_kernel(
    const float* __restrict__ x, __half* __restrict__ hi,
    __half* __restrict__ lo, int n)
{
    int i = (blockIdx.x*256 + threadIdx.x)*4;
    if (i >= n) return;
    float4 v = *(const float4*)&x[i];
    float vv[4] = {v.x, v.y, v.z, v.w};
    __half h[4], l[4];
#pragma unroll
    for (int j = 0; j < 4; j++) {
        h[j] = __float2half_rn(vv[j]);
        l[j] = __float2half_rn(vv[j] - __half2float(h[j]));
    }
    *(uint2*)&hi[i] = *(uint2*)h;
    *(uint2*)&lo[i] = *(uint2*)l;
}

// ---------------------------------------------------------------------------
// Tensor-core GEMM, up to 3 weight matrices in one launch (sel = blockIdx.x>>4)
// C = Ah @ (Bh+Bl) + bias ; 2-pass fp16 split.
// mode 0: row-major C; mode 1: permute into scan layout [b][h][n][k][d]
// CTA tile 128x128, BK=16, 4-stage cp.async, 8 warps of 64x32, 2 CTAs/SM.
// ---------------------------------------------------------------------------
#define LDSM4(R, addr) asm volatile( \
    "ldmatrix.sync.aligned.m8n8.x4.shared.b16 {%0,%1,%2,%3}, [%4];\n" \
    : "=r"((R)[0]), "=r"((R)[1]), "=r"((R)[2]), "=r"((R)[3]) : "r"(addr))
#define LDSM4T(R, addr) asm volatile( \
    "ldmatrix.sync.aligned.m8n8.x4.trans.shared.b16 {%0,%1,%2,%3}, [%4];\n" \
    : "=r"((R)[0]), "=r"((R)[1]), "=r"((R)[2]), "=r"((R)[3]) : "r"(addr))
#define MMA16816H(d, a, b0, b1) asm volatile( \
    "mma.sync.aligned.m16n8k16.row.col.f32.f16.f16.f32 " \
    "{%0,%1,%2,%3},{%4,%5,%6,%7},{%8,%9},{%0,%1,%2,%3};\n" \
    : "+f"((d)[0]), "+f"((d)[1]), "+f"((d)[2]), "+f"((d)[3]) \
    : "r"((a)[0]), "r"((a)[1]), "r"((a)[2]), "r"((a)[3]), "r"(b0), "r"(b1))

// Region byte offsets in dynamic smem (4 stages x 4096B per region)
constexpr uint32_t R_A = 0, R_BH = 16384, R_BL = 32768;
constexpr uint32_t HG_SMEM = 49152;

__global__ __launch_bounds__(256, 2) void hgemm_kernel(
    const __half* __restrict__ Ah,
    const __half* __restrict__ Bh0, const __half* __restrict__ Bl0,
    const float* __restrict__ bias0, float* __restrict__ C0,
    const __half* __restrict__ Bh1, const __half* __restrict__ Bl1,
    const float* __restrict__ bias1, float* __restrict__ C1,
    const __half* __restrict__ Bh2, const __half* __restrict__ Bl2,
    const float* __restrict__ bias2, float* __restrict__ C2,
    int mode)
{
    extern __shared__ __align__(16) unsigned char hsm[];
    const int tid = threadIdx.x, lane = tid & 31, wid = tid >> 5;
    const int wm = wid >> 2, wn = wid & 3;
    const int sel = blockIdx.x >> 4;
    const int row0 = blockIdx.y*128, col0 = (blockIdx.x & 15)*128;
    const __half* Bh = (sel == 0) ? Bh0 : ((sel == 1) ? Bh1 : Bh2);
    const __half* Bl = (sel == 0) ? Bl0 : ((sel == 1) ? Bl1 : Bl2);
    const float* bias = (sel == 0) ? bias0 : ((sel == 1) ? bias1 : bias2);
    float* C = (sel == 0) ? C0 : ((sel == 1) ? C1 : C2);
    const uint32_t sbase = (uint32_t)__cvta_generic_to_shared(hsm);

    // ---- prefetch (global->smem) thread mapping ----
    const int pr = tid >> 1, pc = tid & 1;        // A: row 0..127, chunk 0..1
    const int pk = tid >> 4, pcb = tid & 15;      // B: k 0..15, chunk 0..15
    const __half* gA  = Ah + (size_t)(row0+pr)*Dc + pc*8;
    const __half* gBh = Bh + (size_t)pk*Dc + col0 + pcb*8;
    const __half* gBl = Bl + (size_t)pk*Dc + col0 + pcb*8;
    const uint32_t aoff = (uint32_t)(pr*16 + 8*(pc ^ ((pr>>2)&1)))*2;   // intra-stage
    const uint32_t boff = (uint32_t)(pk*128 + 8*(pcb ^ (pk&7)))*2;

    // ---- ldmatrix per-lane intra-stage offsets ----
    const int ar4 = lane & 15, ac = lane >> 4;
    uint32_t adA[4];
#pragma unroll
    for (int mi = 0; mi < 4; mi++) {
        int r = wm*64 + mi*16 + ar4;
        adA[mi] = (uint32_t)(r*16 + 8*(ac ^ ((r>>2)&1)))*2;
    }
    const int bk = (lane & 7) + ((lane >> 3) & 1)*8;
    uint32_t adB[2];
#pragma unroll
    for (int nj = 0; nj < 2; nj++) {
        int c = wn*4 + nj*2 + ((lane >> 4) & 1);
        adB[nj] = (uint32_t)(bk*128 + 8*(c ^ (bk & 7)))*2;
    }

    float acc[4][4][4];
#pragma unroll
    for (int i = 0; i < 4; i++)
#pragma unroll
        for (int j = 0; j < 4; j++)
#pragma unroll
            for (int k = 0; k < 4; k++) acc[i][j][k] = 0.f;

    constexpr int KT = Dc / 16;   // 128

    auto prefetch = [&](int kt) {
        const uint32_t so = (uint32_t)(kt & 3)*4096;
        const size_t gAo = (size_t)kt*16;
        const size_t gBo = (size_t)kt*16*Dc;
        cp16(sbase + R_A  + so + aoff, gA  + gAo);
        cp16(sbase + R_BH + so + boff, gBh + gBo);
        cp16(sbase + R_BL + so + boff, gBl + gBo);
        asm volatile("cp.async.commit_group;\n");
    };

    prefetch(0);
    prefetch(1);
    prefetch(2);

    for (int kt = 0; kt < KT; kt++) {
        asm volatile("cp.async.wait_group 2;\n");
        __syncthreads();
        if (kt + 3 < KT) prefetch(kt + 3);
        else asm volatile("cp.async.commit_group;\n");

        const uint32_t so = (uint32_t)(kt & 3)*4096;
        uint32_t ar[4][4], bh[2][4], bl[2][4];
#pragma unroll
        for (int mi = 0; mi < 4; mi++)
            LDSM4(ar[mi], sbase + R_A + so + adA[mi]);
#pragma unroll
        for (int nj = 0; nj < 2; nj++) {
            LDSM4T(bh[nj], sbase + R_BH + so + adB[nj]);
            LDSM4T(bl[nj], sbase + R_BL + so + adB[nj]);
        }
#pragma unroll
        for (int mi = 0; mi < 4; mi++) {
#pragma unroll
            for (int ni = 0; ni < 4; ni++) {
                const int q = ni >> 1, hb = (ni & 1)*2;
                MMA16816H(acc[mi][ni], ar[mi], bh[q][hb], bh[q][hb+1]);
                MMA16816H(acc[mi][ni], ar[mi], bl[q][hb], bl[q][hb+1]);
            }
        }
    }

    // ---- epilogue ----
    const int g = lane >> 2, t2 = (lane & 3)*2;
#pragma unroll
    for (int mi = 0; mi < 4; mi++) {
        const int r1 = row0 + wm*64 + mi*16 + g;
        const int r2 = r1 + 8;
#pragma unroll
        for (int ni = 0; ni < 4; ni++) {
            const int col = col0 + wn*32 + ni*8 + t2;
            const float2 bv = *(const float2*)&bias[col];
            float2 v0 = make_float2(acc[mi][ni][0] + bv.x, acc[mi][ni][1] + bv.y);
            float2 v1 = make_float2(acc[mi][ni][2] + bv.x, acc[mi][ni][3] + bv.y);
            if (mode == 0) {
                *(float2*)&C[(size_t)r1*Dc + col] = v0;
                *(float2*)&C[(size_t)r2*Dc + col] = v1;
            } else {
                const int h = col >> 6, d = col & 63;
                {
                    int b = r1 >> 12, l = r1 & 4095, n = l >> 4, kk = l & 15;
                    size_t o = ((((size_t)(b*Hh + h))*NMBc + n)*Kc + kk)*HDc + d;
                    *(float2*)&C[o] = v0;
                }
                {
                    int b = r2 >> 12, l = r2 & 4095, n = l >> 4, kk = l & 15;
                    size_t o = ((((size_t)(b*Hh + h))*NMBc + n)*Kc + kk)*HDc + d;
                    *(float2*)&C[o] = v1;
                }
            }
        }
    }
}

// ---------------------------------------------------------------------------
// lr GEMM: eta[t][h] = sigmoid(hs[t] . lr_w[h] + lr_b[h]) / 1024
// ---------------------------------------------------------------------------
__global__ __launch_bounds__(256) void lr_gemm_kernel(
    const float* __restrict__ hs, const float* __restrict__ lr_w,
    const float* __restrict__ lr_b)
{
    __shared__ float As[32][65];   // [k][token]
    __shared__ float Ws[32][32];   // [k][head]
    const int tid = threadIdx.x;
    const int t0 = blockIdx.x*64;
    const int r0 = (tid >> 4)*4;        // 4 tokens
    const int c0 = (tid & 15)*2;        // 2 heads

    float acc[4][2];
#pragma unroll
    for (int i = 0; i < 4; i++) { acc[i][0] = 0.f; acc[i][1] = 0.f; }

    const int lrow = tid >> 2;              // 0..63
    const int lcol = (tid & 3)*8;           // 0,8,16,24

    for (int k0 = 0; k0 < Dc; k0 += 32) {
        float4 a0 = *(const float4*)&hs[(size_t)(t0+lrow)*Dc + k0 + lcol];
        float4 a1 = *(const float4*)&hs[(size_t)(t0+lrow)*Dc + k0 + lcol + 4];
        float wv[4];
#pragma unroll
        for (int j = 0; j < 4; j++) {
            int i = tid + j*256;
            int h = i >> 5, k = i & 31;
            wv[j] = lr_w[(size_t)h*Dc + k0 + k];
        }
        __syncthreads();
        As[lcol+0][lrow] = a0.x; As[lcol+1][lrow] = a0.y;
        As[lcol+2][lrow] = a0.z; As[lcol+3][lrow] = a0.w;
        As[lcol+4][lrow] = a1.x; As[lcol+5][lrow] = a1.y;
        As[lcol+6][lrow] = a1.z; As[lcol+7][lrow] = a1.w;
#pragma unroll
        for (int j = 0; j < 4; j++) {
            int i = tid + j*256;
            Ws[i & 31][i >> 5] = wv[j];
        }
        __syncthreads();
#pragma unroll 8
        for (int k = 0; k < 32; k++) {
            float w0 = Ws[k][c0], w1 = Ws[k][c0+1];
#pragma unroll
            for (int i = 0; i < 4; i++) {
                float a = As[k][r0+i];
                acc[i][0] += a*w0;
                acc[i][1] += a*w1;
            }
        }
    }

#pragma unroll
    for (int i = 0; i < 4; i++) {
        const int t = t0 + r0 + i;
        const int b = t >> 12, l = t & 4095, n = l >> 4, kk = l & 15;
#pragma unroll
        for (int j = 0; j < 2; j++) {
            const int h = c0 + j;
            float x = acc[i][j] + lr_b[h];
            float sig = 1.f/(1.f+expf(-x));
            g_eta[(((size_t)(b*Hh + h))*NMBc + n)*Kc + kk] = sig * (1.f/1024.f);
        }
    }
}

// ---------------------------------------------------------------------------
// Per (token, head): L2-normalize Q,K; XV <- w*((v-k)-mu)/(std+1e-8)+b+k
// ---------------------------------------------------------------------------
__global__ __launch_bounds__(256) void norm_kernel(
    const float* __restrict__ tnw, const float* __restrict__ tnb)
{
    const int wg   = blockIdx.x*8 + (threadIdx.x >> 5);
    const int lane = threadIdx.x & 31;
    const size_t base = (size_t)wg * 64;
    const int h = (wg >> 12) & 31;

    float q0 = g_q[base+lane], q1 = g_q[base+lane+32];
    float k0 = g_k[base+lane], k1 = g_k[base+lane+32];
    float v0 = g_v[base+lane], v1 = g_v[base+lane+32];

    float s = q0*q0 + q1*q1;
#pragma unroll
    for (int o = 16; o > 0; o >>= 1) s += __shfl_xor_sync(0xffffffffu, s, o);
    float inv = 1.f / fmaxf(sqrtf(s), 1e-12f);
    q0 *= inv; q1 *= inv;

    s = k0*k0 + k1*k1;
#pragma unroll
    for (int o = 16; o > 0; o >>= 1) s += __shfl_xor_sync(0xffffffffu, s, o);
    inv = 1.f / fmaxf(sqrtf(s), 1e-12f);
    k0 *= inv; k1 *= inv;

    float d0 = v0 - k0, d1 = v1 - k1;
    s = d0 + d1;
#pragma unroll
    for (int o = 16; o > 0; o >>= 1) s += __shfl_xor_sync(0xffffffffu, s, o);
    float mu = s * (1.f/64.f);
    float e0 = d0 - mu, e1 = d1 - mu;
    s = e0*e0 + e1*e1;
#pragma unroll
    for (int o = 16; o > 0; o >>= 1) s += __shfl_xor_sync(0xffffffffu, s, o);
    float stdv = sqrtf(s * (1.f/63.f));       // ddof=1
    float den = stdv + 1e-8f;

    float w0 = tnw[h*64+lane], w1 = tnw[h*64+lane+32];
    float b0 = tnb[h*64+lane], b1v = tnb[h*64+lane+32];
    float nv0 = w0*(e0/den) + b0  + k0;
    float nv1 = w1*(e1/den) + b1v + k1;

    g_q[base+lane] = q0; g_q[base+lane+32] = q1;
    g_k[base+lane] = k0; g_k[base+lane+32] = k1;
    g_v[base+lane] = nv0; g_v[base+lane+32] = nv1;
}

// ---------------------------------------------------------------------------
// Sequential TTT scan. One CTA per (b,h). 256 threads.
// Thread = (row r = tid>>4, cols c4 = (tid&15)*4). All LN stats and grads in
// registers via 16-lane shfl. eta folded into stored grad (eg). 3 syncs/step.
// Tiles double-buffered via cp.async.
// ---------------------------------------------------------------------------
constexpr int SM_W1  = 0;
constexpr int SM_B1  = 4096;
constexpr int SM_LNW = 4160;
constexpr int SM_LNB = 4224;
constexpr int SM_EG  = 4288;
constexpr int SM_MS  = 5312;
constexpr int SM_BUF = 5568;
constexpr int BUF_STRIDE = 4176;
constexpr int BO_XQ = 0, BO_XK = 1024, BO_XV = 2048, BO_ETA = 3072, BO_XKT = 3088;
constexpr int SCAN_SMEM = (SM_BUF + 2*BUF_STRIDE)*4;   // 55680 B

__device__ __forceinline__ float rsum16(float v) {
#pragma unroll
    for (int o = 8; o > 0; o >>= 1) v += __shfl_xor_sync(0xffffffffu, v, o);
    return v;
}

__global__ __launch_bounds__(256, 1) void scan_kernel(
    const float* __restrict__ W1g, const float* __restrict__ b1g,
    const float* __restrict__ tnw, const float* __restrict__ tnb)
{
    extern __shared__ __align__(16) float sm[];
    const int bh = blockIdx.x, b = bh >> 5, h = bh & 31;
    const int tid = threadIdx.x;
    const int r = tid >> 4, i2 = tid & 15, c4 = i2*4;

    float* W1s = sm + SM_W1;
    float* b1c = sm + SM_B1;
    float* lnwS = sm + SM_LNW;
    float* lnbS = sm + SM_LNB;
    float* eg  = sm + SM_EG;
    float* Ms  = sm + SM_MS;
    const uint32_t smbase = (uint32_t)__cvta_generic_to_shared(sm);

    for (int i = tid; i < 4096; i += 256) W1s[i] = W1g[(size_t)h*4096 + i];
    if (tid < 64) {
        b1c[tid]  = b1g[h*64 + tid];
        lnwS[tid] = tnw[h*64 + tid];
        lnbS[tid] = tnb[h*64 + tid];
    }

    const size_t tile0 = (size_t)bh * (NMBc*1024);
    const size_t eta0  = (size_t)bh * (NMBc*16);

    // prologue: tile 0 into buf0
    {
        uint32_t d = smbase + (uint32_t)SM_BUF*4;
        cp16(d + BO_XQ*4 + tid*16, g_q + tile0 + (size_t)tid*4);
        cp16(d + BO_XK*4 + tid*16, g_k + tile0 + (size_t)tid*4);
        cp16(d + BO_XV*4 + tid*16, g_v + tile0 + (size_t)tid*4);
        if (tid < 4) cp16(d + BO_ETA*4 + tid*16, g_eta + eta0 + (size_t)tid*4);
        asm volatile("cp.async.commit_group;\n");
        asm volatile("cp.async.wait_group 0;\n");
        // transpose own slice (4 consecutive floats = same row)
        float* bp = sm + SM_BUF;
        {
            int row = tid >> 4;          // (tid*4)>>6
            int col = (tid*4) & 63;
            float4 kvv = *(const float4*)&bp[BO_XK + tid*4];
            bp[BO_XKT + (col+0)*17 + row] = kvv.x;
            bp[BO_XKT + (col+1)*17 + row] = kvv.y;
            bp[BO_XKT + (col+2)*17 + row] = kvv.z;
            bp[BO_XKT + (col+3)*17 + row] = kvv.w;
        }
    }
    __syncthreads();

    for (int n = 0; n < NMBc; n++) {
        float* bp = sm + SM_BUF + (n & 1)*BUF_STRIDE;
        float* np = sm + SM_BUF + ((n+1) & 1)*BUF_STRIDE;
        const bool pf = (n + 1 < NMBc);
        if (pf) {
            uint32_t d = smbase + (uint32_t)(SM_BUF + ((n+1)&1)*BUF_STRIDE)*4;
            size_t tb = tile0 + (size_t)(n+1)*1024;
            cp16(d + BO_XQ*4 + tid*16, g_q + tb + (size_t)tid*4);
            cp16(d + BO_XK*4 + tid*16, g_k + tb + (size_t)tid*4);
            cp16(d + BO_XV*4 + tid*16, g_v + tb + (size_t)tid*4);
            if (tid < 4) cp16(d + BO_ETA*4 + tid*16,
                              g_eta + eta0 + (size_t)(n+1)*16 + (size_t)tid*4);
            asm volatile("cp.async.commit_group;\n");
        }
        const float* xq  = bp + BO_XQ;
        const float* xk  = bp + BO_XK;
        const float* xv  = bp + BO_XV;
        const float* et  = bp + BO_ETA;
        const float* xkT = bp + BO_XKT;

        const float4 bb = *(const float4*)&b1c[c4];
        const float4 lw = *(const float4*)&lnwS[c4];
        const float4 lb = *(const float4*)&lnbS[c4];

        // ---- P1: Z1 = xk@W1 + b1 (row r, cols c4..c4+3) ----
        float4 z = bb;
#pragma unroll 8
        for (int k = 0; k < 64; k++) {
            float x = xk[r*64 + k];
            float4 w = *(const float4*)&W1s[k*64 + c4];
            z.x += x*w.x; z.y += x*w.y; z.z += x*w.z; z.w += x*w.w;
        }
        float mu = rsum16(z.x+z.y+z.z+z.w) * (1.f/64.f);
        float dx = z.x-mu, dy = z.y-mu, dz = z.z-mu, dw = z.w-mu;
        float var = rsum16(dx*dx+dy*dy+dz*dz+dw*dw) * (1.f/64.f);
        float stdv = sqrtf(var + 1e-6f);
        float inv = 1.f/stdv;
        float4 xh = make_float4(dx*inv, dy*inv, dz*inv, dw*inv);
        const float4 kv = *(const float4*)&xk[r*64 + c4];
        const float4 vv = *(const float4*)&xv[r*64 + c4];
        float4 gx;
        gx.x = (lw.x*xh.x + lb.x - (vv.x - kv.x))*lw.x;
        gx.y = (lw.y*xh.y + lb.y - (vv.y - kv.y))*lw.y;
        gx.z = (lw.z*xh.z + lb.z - (vv.z - kv.z))*lw.z;
        gx.w = (lw.w*xh.w + lb.w - (vv.w - kv.w))*lw.w;
        float s1 = rsum16(gx.x+gx.y+gx.z+gx.w);
        float s2 = rsum16(gx.x*xh.x + gx.y*xh.y + gx.z*xh.z + gx.w*xh.w);
        float sc = et[r] / (64.f*stdv);      // eta folded in
        float4 egv;
        egv.x = (64.f*gx.x - s1 - xh.x*s2)*sc;
        egv.y = (64.f*gx.y - s1 - xh.y*s2)*sc;
        egv.z = (64.f*gx.z - s1 - xh.z*s2)*sc;
        egv.w = (64.f*gx.w - s1 - xh.w*s2)*sc;
        *(float4*)&eg[r*64 + c4] = egv;
        // M'[r][j] = (xq[r].xk[j] + 1) for j<=r else 0   (j = i2)
        {
            float d = 0.f;
#pragma unroll 8
            for (int k = 0; k < 64; k++) d += xq[r*64 + k]*xkT[k*17 + i2];
            Ms[r*16 + i2] = (i2 <= r) ? (d + 1.f) : 0.f;
        }
        __syncthreads();

        // ---- P2: Z1_bar = xq@W1 + b1 - M'@eg ----
        float4 zb = bb;
#pragma unroll 8
        for (int k = 0; k < 64; k++) {
            float x = xq[r*64 + k];
            float4 w = *(const float4*)&W1s[k*64 + c4];
            zb.x += x*w.x; zb.y += x*w.y; zb.z += x*w.z; zb.w += x*w.w;
        }
#pragma unroll
        for (int j = 0; j < 16; j++) {
            float m = Ms[r*16 + j];
            float4 g4 = *(const float4*)&eg[j*64 + c4];
            zb.x -= m*g4.x; zb.y -= m*g4.y; zb.z -= m*g4.z; zb.w -= m*g4.w;
        }
        float mu2 = rsum16(zb.x+zb.y+zb.z+zb.w) * (1.f/64.f);
        float ex = zb.x-mu2, ey = zb.y-mu2, ez = zb.z-mu2, ew = zb.w-mu2;
        float var2 = rsum16(ex*ex+ey*ey+ez*ez+ew*ew) * (1.f/64.f);
        float inv2 = rsqrtf(var2 + 1e-6f);
        const float4 q4v = *(const float4*)&xq[r*64 + c4];
        float4 out;
        out.x = q4v.x + ex*inv2*lw.x + lb.x;
        out.y = q4v.y + ey*inv2*lw.y + lb.y;
        out.z = q4v.z + ez*inv2*lw.z + lb.z;
        out.w = q4v.w + ew*inv2*lw.w + lb.w;
        *(float4*)&g_y[((size_t)b*Lc + n*Kc + r)*Dc + h*HDc + c4] = out;
        __syncthreads();

        // ---- P3: state update. Thread handles k in {r, r+16, r+32, r+48} ----
        {
            float4 a0 = make_float4(0,0,0,0), a1 = a0, a2 = a0, a3 = a0, bs = a0;
#pragma unroll
            for (int j = 0; j < 16; j++) {
                float4 g4 = *(const float4*)&eg[j*64 + c4];
                float x0 = xkT[(r   )*17 + j];
                float x1 = xkT[(r+16)*17 + j];
                float x2 = xkT[(r+32)*17 + j];
                float x3 = xkT[(r+48)*17 + j];
                a0.x += x0*g4.x; a0.y += x0*g4.y; a0.z += x0*g4.z; a0.w += x0*g4.w;
                a1.x += x1*g4.x; a1.y += x1*g4.y; a1.z += x1*g4.z; a1.w += x1*g4.w;
                a2.x += x2*g4.x; a2.y += x2*g4.y; a2.z += x2*g4.z; a2.w += x2*g4.w;
                a3.x += x3*g4.x; a3.y += x3*g4.y; a3.z += x3*g4.z; a3.w += x3*g4.w;
                bs.x += g4.x; bs.y += g4.y; bs.z += g4.z; bs.w += g4.w;
            }
            float4 w;
            w = *(const float4*)&W1s[(r   )*64 + c4];
            w.x -= a0.x; w.y -= a0.y; w.z -= a0.z; w.w -= a0.w;
            *(float4*)&W1s[(r   )*64 + c4] = w;
            w = *(const float4*)&W1s[(r+16)*64 + c4];
            w.x -= a1.x; w.y -= a1.y; w.z -= a1.z; w.w -= a1.w;
            *(float4*)&W1s[(r+16)*64 + c4] = w;
            w = *(const float4*)&W1s[(r+32)*64 + c4];
            w.x -= a2.x; w.y -= a2.y; w.z -= a2.z; w.w -= a2.w;
            *(float4*)&W1s[(r+32)*64 + c4] = w;
            w = *(const float4*)&W1s[(r+48)*64 + c4];
            w.x -= a3.x; w.y -= a3.y; w.z -= a3.z; w.w -= a3.w;
            *(float4*)&W1s[(r+48)*64 + c4] = w;
            if (r == 0) {
                float4 bo = bb;
                bo.x -= bs.x; bo.y -= bs.y; bo.z -= bs.z; bo.w -= bs.w;
                *(float4*)&b1c[c4] = bo;
            }
        }
        // ---- drain next tile; transpose own xk slice ----
        if (pf) {
            asm volatile("cp.async.wait_group 0;\n");
            int row = tid >> 4;
            int col = (tid*4) & 63;
            float4 kvv = *(const float4*)&np[BO_XK + tid*4];
            np[BO_XKT + (col+0)*17 + row] = kvv.x;
            np[BO_XKT + (col+1)*17 + row] = kvv.y;
            np[BO_XKT + (col+2)*17 + row] = kvv.z;
            np[BO_XKT + (col+3)*17 + row] = kvv.w;
        }
        __syncthreads();
    }
}

// ---------------------------------------------------------------------------
// Post layernorm over D=2048 per token; emits fp16 hi directly.
// ---------------------------------------------------------------------------
__global__ __launch_bounds__(256) void postnorm_kernel(
    const float* __restrict__ pw, const float* __restrict__ pb)
{
    __shared__ float red[8];
    __shared__ float smu, svar;
    const int row = blockIdx.x, tid = threadIdx.x;
    const int lane = tid & 31, wid = tid >> 5;
    const float* x = g_y + (size_t)row*Dc;

    float v[8];
    *(float4*)(v)   = *(const float4*)&x[tid*8];
    *(float4*)(v+4) = *(const float4*)&x[tid*8+4];

    float s = v[0]+v[1]+v[2]+v[3]+v[4]+v[5]+v[6]+v[7];
#pragma unroll
    for (int o = 16; o > 0; o >>= 1) s += __shfl_xor_sync(0xffffffffu, s, o);
    if (lane == 0) red[wid] = s;
    __syncthreads();
    if (tid == 0) {
        float t = 0.f;
#pragma unroll
        for (int i = 0; i < 8; i++) t += red[i];
        smu = t * (1.f/2048.f);
    }
    __syncthreads();
    float mu = smu;

    float ss = 0.f;
#pragma unroll
    for (int i = 0; i < 8; i++) { float d = v[i]-mu; ss += d*d; }
#pragma unroll
    for (int o = 16; o > 0; o >>= 1) ss += __shfl_xor_sync(0xffffffffu, ss, o);
    if (lane == 0) red[wid] = ss;
    __syncthreads();
    if (tid == 0) {
        float t = 0.f;
#pragma unroll
        for (int i = 0; i < 8; i++) t += red[i];
        svar = t * (1.f/2048.f);
    }
    __syncthreads();
    float rstd = rsqrtf(svar + 1e-6f);

    __half hb[8];
#pragma unroll
    for (int i = 0; i < 8; i++) {
        int cc = tid*8 + i;
        float y = (v[i]-mu)*rstd*pw[cc] + pb[cc];
        hb[i] = __float2half_rn(y);
    }
    *(uint4*)&g_xnh[(size_t)row*Dc + tid*8] = *(uint4*)hb;
}

// ---------------------------------------------------------------------------
extern "C" void kernel_launch(void* const* d_in, const int* in_sizes, int n_in,
                              void* d_out, int out_size)
{
    (void)in_sizes; (void)n_in; (void)out_size;
    const float* hs    = (const float*)d_in[0];
    const float* wq_w  = (const float*)d_in[1];
    const float* wq_b  = (const float*)d_in[2];
    const float* wk_w  = (const float*)d_in[3];
    const float* wk_b  = (const float*)d_in[4];
    const float* wv_w  = (const float*)d_in[5];
    const float* wv_b  = (const float*)d_in[6];
    const float* wo_w  = (const float*)d_in[7];
    const float* wo_b  = (const float*)d_in[8];
    const float* tnw   = (const float*)d_in[9];
    const float* tnb   = (const float*)d_in[10];
    const float* lr_w  = (const float*)d_in[11];
    const float* lr_b  = (const float*)d_in[12];
    const float* W1    = (const float*)d_in[13];
    const float* b1    = (const float*)d_in[14];
    const float* pnw   = (const float*)d_in[15];
    const float* pnb   = (const float*)d_in[16];

    float *pq, *pk, *pv;
    __half *ah, *wqh, *wql, *wkh, *wkl, *wvh, *wvl, *woh, *wol, *xnh;
    cudaGetSymbolAddress((void**)&pq,  g_q);
    cudaGetSymbolAddress((void**)&pk,  g_k);
    cudaGetSymbolAddress((void**)&pv,  g_v);
    cudaGetSymbolAddress((void**)&ah,  g_ah);
    cudaGetSymbolAddress((void**)&wqh, g_wqh);
    cudaGetSymbolAddress((void**)&wql, g_wql);
    cudaGetSymbolAddress((void**)&wkh, g_wkh);
    cudaGetSymbolAddress((void**)&wkl, g_wkl);
    cudaGetSymbolAddress((void**)&wvh, g_wvh);
    cudaGetSymbolAddress((void**)&wvl, g_wvl);
    cudaGetSymbolAddress((void**)&woh, g_woh);
    cudaGetSymbolAddress((void**)&wol, g_wol);
    cudaGetSymbolAddress((void**)&xnh, g_xnh);

    cudaFuncSetAttribute(hgemm_kernel,
                         cudaFuncAttributeMaxDynamicSharedMemorySize, HG_SMEM);
    cudaFuncSetAttribute(scan_kernel,
                         cudaFuncAttributeMaxDynamicSharedMemorySize, SCAN_SMEM);

    const int nA = Mrows*Dc;     // 16.7M
    const int nW = Dc*Dc;        // 4.2M
    conv_hi_kernel<<<nA/1024, 256>>>(hs, ah, nA);
    conv_hilo_kernel<<<nW/1024, 256>>>(wq_w, wqh, wql, nW);
    conv_hilo_kernel<<<nW/1024, 256>>>(wk_w, wkh, wkl, nW);
    conv_hilo_kernel<<<nW/1024, 256>>>(wv_w, wvh, wvl, nW);
    conv_hilo_kernel<<<nW/1024, 256>>>(wo_w, woh, wol, nW);

    // merged QKV GEMM: grid.x = 3 matrices x 16 col-tiles
    hgemm_kernel<<<dim3(48, 64), 256, HG_SMEM>>>(
        ah,
        wqh, wql, wq_b, pq,
        wkh, wkl, wk_b, pk,
        wvh, wvl, wv_b, pv,
        1);
    lr_gemm_kernel<<<Mrows/64, 256>>>(hs, lr_w, lr_b);
    norm_kernel<<<(Bb*Hh*NMBc*Kc)/8, 256>>>(tnw, tnb);
    scan_kernel<<<Bb*Hh, 256, SCAN_SMEM>>>(W1, b1, tnw, tnb);
    postnorm_kernel<<<Mrows, 256>>>(pnw, pnb);
    hgemm_kernel<<<dim3(16, 64), 256, HG_SMEM>>>(
        xnh,
        woh, wol, wo_b, (float*)d_out,
        woh, wol, wo_b, (float*)d_out,
        woh, wol, wo_b, (float*)d_out,
        0);
}

// round 8
// speedup vs baseline: 1.4941x; 1.4941x over previous
#include <cuda_runtime.h>
#include <cuda_fp16.h>
#include <math.h>
#include <stdint.h>

// Problem constants (fixed shapes)
constexpr int Bb  = 2;
constexpr int Lc  = 4096;
constexpr int Dc  = 2048;
constexpr int Hh  = 32;
constexpr int Kc  = 16;
constexpr int HDc = 64;
constexpr int NMBc = 256;           // L / K
constexpr int Mrows = Bb * Lc;      // 8192

// Scratch (device globals; allocation in kernel_launch is forbidden)
__device__ float g_q  [(size_t)Bb*Hh*NMBc*Kc*HDc];   // scan layout [b][h][n][k][d]
__device__ float g_k  [(size_t)Bb*Hh*NMBc*Kc*HDc];
__device__ float g_v  [(size_t)Bb*Hh*NMBc*Kc*HDc];
__device__ float g_eta[(size_t)Bb*Hh*NMBc*Kc];
__device__ float g_y  [(size_t)Bb*Lc*Dc];            // scan output, token layout

// fp16 operands for tensor-core GEMMs (A: hi only; W: hi/lo split)
__device__ __half g_ah [(size_t)Mrows*Dc];
__device__ __half g_wqh[(size_t)Dc*Dc];
__device__ __half g_wql[(size_t)Dc*Dc];
__device__ __half g_wkh[(size_t)Dc*Dc];
__device__ __half g_wkl[(size_t)Dc*Dc];
__device__ __half g_wvh[(size_t)Dc*Dc];
__device__ __half g_wvl[(size_t)Dc*Dc];
__device__ __half g_woh[(size_t)Dc*Dc];
__device__ __half g_wol[(size_t)Dc*Dc];
__device__ __half g_xnh[(size_t)Mrows*Dc];

__device__ __forceinline__ void cp16(uint32_t dst, const void* src) {
    asm volatile("cp.async.cg.shared.global [%0], [%1], 16;\n" :: "r"(dst), "l"(src));
}

// ---------------------------------------------------------------------------
// fp32 -> fp16 (hi only).  n multiple of 1024.
// ---------------------------------------------------------------------------
__global__ __launch_bounds__(256) void conv_hi_kernel(
    const float* __restrict__ x, __half* __restrict__ hi, int n)
{
    int i = (blockIdx.x*256 + threadIdx.x)*4;
    if (i >= n) return;
    float4 v = *(const float4*)&x[i];
    __half h[4];
    h[0] = __float2half_rn(v.x); h[1] = __float2half_rn(v.y);
    h[2] = __float2half_rn(v.z); h[3] = __float2half_rn(v.w);
    *(uint2*)&hi[i] = *(uint2*)h;
}

// ---------------------------------------------------------------------------
// fp32 -> fp16 (hi, lo) split.  n multiple of 1024.
// ---------------------------------------------------------------------------
__global__ __launch_bounds__(256) void conv_hilo_kernel(
    const float* __restrict__ x, __half* __restrict__ hi,
    __half* __restrict__ lo, int n)
{
    int i = (blockIdx.x*256 + threadIdx.x)*4;
    if (i >= n) return;
    float4 v = *(const float4*)&x[i];
    float vv[4] = {v.x, v.y, v.z, v.w};
    __half h[4], l[4];
#pragma unroll
    for (int j = 0; j < 4; j++) {
        h[j] = __float2half_rn(vv[j]);
        l[j] = __float2half_rn(vv[j] - __half2float(h[j]));
    }
    *(uint2*)&hi[i] = *(uint2*)h;
    *(uint2*)&lo[i] = *(uint2*)l;
}

// ---------------------------------------------------------------------------
// Tensor-core GEMM: C = A @ (Bh+Bl) + bias ; 2-pass fp16 split.
// mode 1: merged QKV (sel = blockIdx.x>>4 picks weights/bias/output from
//         device symbols), permuted epilogue into scan layout.
// mode 0: output GEMM (A=g_xnh, W=g_wo*, C=Cout), row-major epilogue.
// CTA tile 128x128, BK=16, 4-stage cp.async, 8 warps of 64x32, 2 CTAs/SM.
// ---------------------------------------------------------------------------
#define LDSM4(R, addr) asm volatile( \
    "ldmatrix.sync.aligned.m8n8.x4.shared.b16 {%0,%1,%2,%3}, [%4];\n" \
    : "=r"((R)[0]), "=r"((R)[1]), "=r"((R)[2]), "=r"((R)[3]) : "r"(addr))
#define LDSM4T(R, addr) asm volatile( \
    "ldmatrix.sync.aligned.m8n8.x4.trans.shared.b16 {%0,%1,%2,%3}, [%4];\n" \
    : "=r"((R)[0]), "=r"((R)[1]), "=r"((R)[2]), "=r"((R)[3]) : "r"(addr))
#define MMA16816H(d, a, b0, b1) asm volatile( \
    "mma.sync.aligned.m16n8k16.row.col.f32.f16.f16.f32 " \
    "{%0,%1,%2,%3},{%4,%5,%6,%7},{%8,%9},{%0,%1,%2,%3};\n" \
    : "+f"((d)[0]), "+f"((d)[1]), "+f"((d)[2]), "+f"((d)[3]) \
    : "r"((a)[0]), "r"((a)[1]), "r"((a)[2]), "r"((a)[3]), "r"(b0), "r"(b1))

// Region byte offsets in dynamic smem (4 stages x 4096B per region)
constexpr uint32_t R_A = 0, R_BH = 16384, R_BL = 32768;
constexpr uint32_t HG_SMEM = 49152;

__global__ __launch_bounds__(256, 2) void hgemm_kernel(
    const float* __restrict__ bias0, const float* __restrict__ bias1,
    const float* __restrict__ bias2, float* __restrict__ Cout, int mode)
{
    extern __shared__ __align__(16) unsigned char hsm[];
    const int tid = threadIdx.x, lane = tid & 31, wid = tid >> 5;
    const int wm = wid >> 2, wn = wid & 3;
    const int row0 = blockIdx.y*128, col0 = (blockIdx.x & 15)*128;

    const __half* Ah;
    const __half* Bh;
    const __half* Bl;
    const float* bias;
    float* C;
    if (mode == 1) {
        const int sel = blockIdx.x >> 4;
        Ah = g_ah;
        Bh = (sel == 0) ? g_wqh : ((sel == 1) ? g_wkh : g_wvh);
        Bl = (sel == 0) ? g_wql : ((sel == 1) ? g_wkl : g_wvl);
        bias = (sel == 0) ? bias0 : ((sel == 1) ? bias1 : bias2);
        C = (sel == 0) ? g_q : ((sel == 1) ? g_k : g_v);
    } else {
        Ah = g_xnh; Bh = g_woh; Bl = g_wol; bias = bias0; C = Cout;
    }
    const uint32_t sbase = (uint32_t)__cvta_generic_to_shared(hsm);

    // ---- prefetch (global->smem) thread mapping ----
    const int pr = tid >> 1, pc = tid & 1;        // A: row 0..127, chunk 0..1
    const int pk = tid >> 4, pcb = tid & 15;      // B: k 0..15, chunk 0..15
    const __half* gA  = Ah + (size_t)(row0+pr)*Dc + pc*8;
    const __half* gBh = Bh + (size_t)pk*Dc + col0 + pcb*8;
    const __half* gBl = Bl + (size_t)pk*Dc + col0 + pcb*8;
    const uint32_t aoff = (uint32_t)(pr*16 + 8*(pc ^ ((pr>>2)&1)))*2;   // intra-stage
    const uint32_t boff = (uint32_t)(pk*128 + 8*(pcb ^ (pk&7)))*2;

    // ---- ldmatrix per-lane intra-stage offsets ----
    const int ar4 = lane & 15, ac = lane >> 4;
    uint32_t adA[4];
#pragma unroll
    for (int mi = 0; mi < 4; mi++) {
        int r = wm*64 + mi*16 + ar4;
        adA[mi] = (uint32_t)(r*16 + 8*(ac ^ ((r>>2)&1)))*2;
    }
    const int bk = (lane & 7) + ((lane >> 3) & 1)*8;
    uint32_t adB[2];
#pragma unroll
    for (int nj = 0; nj < 2; nj++) {
        int c = wn*4 + nj*2 + ((lane >> 4) & 1);
        adB[nj] = (uint32_t)(bk*128 + 8*(c ^ (bk & 7)))*2;
    }

    float acc[4][4][4];
#pragma unroll
    for (int i = 0; i < 4; i++)
#pragma unroll
        for (int j = 0; j < 4; j++)
#pragma unroll
            for (int k = 0; k < 4; k++) acc[i][j][k] = 0.f;

    constexpr int KT = Dc / 16;   // 128

    auto prefetch = [&](int kt) {
        const uint32_t so = (uint32_t)(kt & 3)*4096;
        const size_t gAo = (size_t)kt*16;
        const size_t gBo = (size_t)kt*16*Dc;
        cp16(sbase + R_A  + so + aoff, gA  + gAo);
        cp16(sbase + R_BH + so + boff, gBh + gBo);
        cp16(sbase + R_BL + so + boff, gBl + gBo);
        asm volatile("cp.async.commit_group;\n");
    };

    prefetch(0);
    prefetch(1);
    prefetch(2);

    for (int kt = 0; kt < KT; kt++) {
        asm volatile("cp.async.wait_group 2;\n");
        __syncthreads();
        if (kt + 3 < KT) prefetch(kt + 3);
        else asm volatile("cp.async.commit_group;\n");

        const uint32_t so = (uint32_t)(kt & 3)*4096;
        uint32_t ar[4][4], bh[2][4], bl[2][4];
#pragma unroll
        for (int mi = 0; mi < 4; mi++)
            LDSM4(ar[mi], sbase + R_A + so + adA[mi]);
#pragma unroll
        for (int nj = 0; nj < 2; nj++) {
            LDSM4T(bh[nj], sbase + R_BH + so + adB[nj]);
            LDSM4T(bl[nj], sbase + R_BL + so + adB[nj]);
        }
#pragma unroll
        for (int mi = 0; mi < 4; mi++) {
#pragma unroll
            for (int ni = 0; ni < 4; ni++) {
                const int q = ni >> 1, hb = (ni & 1)*2;
                MMA16816H(acc[mi][ni], ar[mi], bh[q][hb], bh[q][hb+1]);
                MMA16816H(acc[mi][ni], ar[mi], bl[q][hb], bl[q][hb+1]);
            }
        }
    }

    // ---- epilogue ----
    const int g = lane >> 2, t2 = (lane & 3)*2;
#pragma unroll
    for (int mi = 0; mi < 4; mi++) {
        const int r1 = row0 + wm*64 + mi*16 + g;
        const int r2 = r1 + 8;
#pragma unroll
        for (int ni = 0; ni < 4; ni++) {
            const int col = col0 + wn*32 + ni*8 + t2;
            const float2 bv = *(const float2*)&bias[col];
            float2 v0 = make_float2(acc[mi][ni][0] + bv.x, acc[mi][ni][1] + bv.y);
            float2 v1 = make_float2(acc[mi][ni][2] + bv.x, acc[mi][ni][3] + bv.y);
            if (mode == 0) {
                *(float2*)&C[(size_t)r1*Dc + col] = v0;
                *(float2*)&C[(size_t)r2*Dc + col] = v1;
            } else {
                const int h = col >> 6, d = col & 63;
                {
                    int b = r1 >> 12, l = r1 & 4095, n = l >> 4, kk = l & 15;
                    size_t o = ((((size_t)(b*Hh + h))*NMBc + n)*Kc + kk)*HDc + d;
                    *(float2*)&C[o] = v0;
                }
                {
                    int b = r2 >> 12, l = r2 & 4095, n = l >> 4, kk = l & 15;
                    size_t o = ((((size_t)(b*Hh + h))*NMBc + n)*Kc + kk)*HDc + d;
                    *(float2*)&C[o] = v1;
                }
            }
        }
    }
}

// ---------------------------------------------------------------------------
// lr GEMM: eta[t][h] = sigmoid(hs[t] . lr_w[h] + lr_b[h]) / 1024
// ---------------------------------------------------------------------------
__global__ __launch_bounds__(256) void lr_gemm_kernel(
    const float* __restrict__ hs, const float* __restrict__ lr_w,
    const float* __restrict__ lr_b)
{
    __shared__ float As[32][65];   // [k][token]
    __shared__ float Ws[32][32];   // [k][head]
    const int tid = threadIdx.x;
    const int t0 = blockIdx.x*64;
    const int r0 = (tid >> 4)*4;        // 4 tokens
    const int c0 = (tid & 15)*2;        // 2 heads

    float acc[4][2];
#pragma unroll
    for (int i = 0; i < 4; i++) { acc[i][0] = 0.f; acc[i][1] = 0.f; }

    const int lrow = tid >> 2;              // 0..63
    const int lcol = (tid & 3)*8;           // 0,8,16,24

    for (int k0 = 0; k0 < Dc; k0 += 32) {
        float4 a0 = *(const float4*)&hs[(size_t)(t0+lrow)*Dc + k0 + lcol];
        float4 a1 = *(const float4*)&hs[(size_t)(t0+lrow)*Dc + k0 + lcol + 4];
        float wv[4];
#pragma unroll
        for (int j = 0; j < 4; j++) {
            int i = tid + j*256;
            int h = i >> 5, k = i & 31;
            wv[j] = lr_w[(size_t)h*Dc + k0 + k];
        }
        __syncthreads();
        As[lcol+0][lrow] = a0.x; As[lcol+1][lrow] = a0.y;
        As[lcol+2][lrow] = a0.z; As[lcol+3][lrow] = a0.w;
        As[lcol+4][lrow] = a1.x; As[lcol+5][lrow] = a1.y;
        As[lcol+6][lrow] = a1.z; As[lcol+7][lrow] = a1.w;
#pragma unroll
        for (int j = 0; j < 4; j++) {
            int i = tid + j*256;
            Ws[i & 31][i >> 5] = wv[j];
        }
        __syncthreads();
#pragma unroll 8
        for (int k = 0; k < 32; k++) {
            float w0 = Ws[k][c0], w1 = Ws[k][c0+1];
#pragma unroll
            for (int i = 0; i < 4; i++) {
                float a = As[k][r0+i];
                acc[i][0] += a*w0;
                acc[i][1] += a*w1;
            }
        }
    }

#pragma unroll
    for (int i = 0; i < 4; i++) {
        const int t = t0 + r0 + i;
        const int b = t >> 12, l = t & 4095, n = l >> 4, kk = l & 15;
#pragma unroll
        for (int j = 0; j < 2; j++) {
            const int h = c0 + j;
            float x = acc[i][j] + lr_b[h];
            float sig = 1.f/(1.f+expf(-x));
            g_eta[(((size_t)(b*Hh + h))*NMBc + n)*Kc + kk] = sig * (1.f/1024.f);
        }
    }
}

// ---------------------------------------------------------------------------
// Per (token, head): L2-normalize Q,K; XV <- w*((v-k)-mu)/(std+1e-8)+b+k
// ---------------------------------------------------------------------------
__global__ __launch_bounds__(256) void norm_kernel(
    const float* __restrict__ tnw, const float* __restrict__ tnb)
{
    const int wg   = blockIdx.x*8 + (threadIdx.x >> 5);
    const int lane = threadIdx.x & 31;
    const size_t base = (size_t)wg * 64;
    const int h = (wg >> 12) & 31;

    float q0 = g_q[base+lane], q1 = g_q[base+lane+32];
    float k0 = g_k[base+lane], k1 = g_k[base+lane+32];
    float v0 = g_v[base+lane], v1 = g_v[base+lane+32];

    float s = q0*q0 + q1*q1;
#pragma unroll
    for (int o = 16; o > 0; o >>= 1) s += __shfl_xor_sync(0xffffffffu, s, o);
    float inv = 1.f / fmaxf(sqrtf(s), 1e-12f);
    q0 *= inv; q1 *= inv;

    s = k0*k0 + k1*k1;
#pragma unroll
    for (int o = 16; o > 0; o >>= 1) s += __shfl_xor_sync(0xffffffffu, s, o);
    inv = 1.f / fmaxf(sqrtf(s), 1e-12f);
    k0 *= inv; k1 *= inv;

    float d0 = v0 - k0, d1 = v1 - k1;
    s = d0 + d1;
#pragma unroll
    for (int o = 16; o > 0; o >>= 1) s += __shfl_xor_sync(0xffffffffu, s, o);
    float mu = s * (1.f/64.f);
    float e0 = d0 - mu, e1 = d1 - mu;
    s = e0*e0 + e1*e1;
#pragma unroll
    for (int o = 16; o > 0; o >>= 1) s += __shfl_xor_sync(0xffffffffu, s, o);
    float stdv = sqrtf(s * (1.f/63.f));       // ddof=1
    float den = stdv + 1e-8f;

    float w0 = tnw[h*64+lane], w1 = tnw[h*64+lane+32];
    float b0 = tnb[h*64+lane], b1v = tnb[h*64+lane+32];
    float nv0 = w0*(e0/den) + b0  + k0;
    float nv1 = w1*(e1/den) + b1v + k1;

    g_q[base+lane] = q0; g_q[base+lane+32] = q1;
    g_k[base+lane] = k0; g_k[base+lane+32] = k1;
    g_v[base+lane] = nv0; g_v[base+lane+32] = nv1;
}

// ---------------------------------------------------------------------------
// Sequential TTT scan. One CTA per (b,h). 256 threads. Register prefetch of
// tile n+1 hides global latency.  (R5 proven version)
// ---------------------------------------------------------------------------
__global__ __launch_bounds__(256) void scan_kernel(
    const float* __restrict__ W1g, const float* __restrict__ b1g,
    const float* __restrict__ tnw, const float* __restrict__ tnb)
{
    __shared__ __align__(16) float W1s[64*64];
    __shared__ __align__(16) float xqs[1024];
    __shared__ __align__(16) float xks[1024];
    __shared__ __align__(16) float xvs[1024];
    __shared__ __align__(16) float grads[1024];
    __shared__ __align__(16) float zs[1024];
    __shared__ __align__(16) float xhs[1024];
    __shared__ __align__(16) float xkTs[64*17];
    __shared__ __align__(16) float Ms[256];
    __shared__ float b1s[64], lnw[64], lnb[64], etas[16];
    __shared__ float mus[16], stds[16], sg1[16], sg2[16], mu2[16], std2[16];

    const int bh = blockIdx.x;
    const int b = bh >> 5, h = bh & 31;
    const int tid = threadIdx.x;
    const int c = tid & 63, q4 = tid >> 6;
    const int r0 = q4 * 4;

    for (int i = tid; i < 4096; i += 256) W1s[i] = W1g[(size_t)h*4096 + i];
    if (tid < 64) {
        b1s[tid] = b1g[h*64 + tid];
        lnw[tid] = tnw[h*64 + tid];
        lnb[tid] = tnb[h*64 + tid];
    }

    const size_t tile0 = (size_t)bh * (NMBc * 1024);

    for (int j = 0; j < 4; j++) {
        int idx = tid + j*256;
        float vq = g_q[tile0+idx];
        float vk = g_k[tile0+idx];
        float vv = g_v[tile0+idx];
        xqs[idx] = vq; xks[idx] = vk; xvs[idx] = vv;
        xkTs[(idx & 63)*17 + (idx >> 6)] = vk;
    }
    if (tid < 16) etas[tid] = g_eta[(size_t)bh*NMBc*Kc + tid];
    __syncthreads();

    for (int n = 0; n < NMBc; n++) {
        float rq[4], rk[4], rv[4], re = 0.f;
        const bool pf = (n + 1 < NMBc);
        if (pf) {
            const size_t tb = tile0 + (size_t)(n+1)*1024;
#pragma unroll
            for (int j = 0; j < 4; j++) {
                rq[j] = g_q[tb + tid + j*256];
                rk[j] = g_k[tb + tid + j*256];
                rv[j] = g_v[tb + tid + j*256];
            }
            if (tid < 16) re = g_eta[((size_t)bh*NMBc + n+1)*Kc + tid];
        }

        // ---- Z1 = xk @ W1 + b1 ----
        {
            float a0=0.f,a1=0.f,a2=0.f,a3=0.f;
#pragma unroll 8
            for (int k = 0; k < 64; k++) {
                float w = W1s[k*64 + c];
                a0 += xks[(r0+0)*64+k]*w;
                a1 += xks[(r0+1)*64+k]*w;
                a2 += xks[(r0+2)*64+k]*w;
                a3 += xks[(r0+3)*64+k]*w;
            }
            float bb = b1s[c];
            zs[(r0+0)*64+c] = a0+bb;
            zs[(r0+1)*64+c] = a1+bb;
            zs[(r0+2)*64+c] = a2+bb;
            zs[(r0+3)*64+c] = a3+bb;
        }
        __syncthreads();

        // ---- row stats of Z1 ----
        {
            int r = tid >> 4, i2 = tid & 15;
            float4 v = *(const float4*)&zs[r*64 + i2*4];
            float s = v.x+v.y+v.z+v.w;
#pragma unroll
            for (int o = 8; o > 0; o >>= 1) s += __shfl_xor_sync(0xffffffffu, s, o);
            float mu = s * (1.f/64.f);
            float dx=v.x-mu, dy=v.y-mu, dz=v.z-mu, dw=v.w-mu;
            float ss = dx*dx+dy*dy+dz*dz+dw*dw;
#pragma unroll
            for (int o = 8; o > 0; o >>= 1) ss += __shfl_xor_sync(0xffffffffu, ss, o);
            if (i2 == 0) { mus[r] = mu; stds[r] = sqrtf(ss*(1.f/64.f) + 1e-6f); }
        }
        __syncthreads();

        // ---- x_hat + grad_x_hat ----
        for (int j = 0; j < 4; j++) {
            int idx = tid + j*256;
            int r = idx >> 6, cc = idx & 63;
            float xh = (zs[idx] - mus[r]) / stds[r];
            float target = xvs[idx] - xks[idx];
            float gxh = (lnw[cc]*xh + lnb[cc] - target) * lnw[cc];
            xhs[idx] = xh;
            zs[idx]  = gxh;
        }
        __syncthreads();

        // ---- row sums: sum(gxh), sum(xh*gxh) ----
        {
            int r = tid >> 4, i2 = tid & 15;
            float4 g4 = *(const float4*)&zs [r*64 + i2*4];
            float4 x4 = *(const float4*)&xhs[r*64 + i2*4];
            float s1 = g4.x+g4.y+g4.z+g4.w;
            float s2 = g4.x*x4.x + g4.y*x4.y + g4.z*x4.z + g4.w*x4.w;
#pragma unroll
            for (int o = 8; o > 0; o >>= 1) {
                s1 += __shfl_xor_sync(0xffffffffu, s1, o);
                s2 += __shfl_xor_sync(0xffffffffu, s2, o);
            }
            if (i2 == 0) { sg1[r] = s1; sg2[r] = s2; }
        }
        __syncthreads();

        // ---- grad ----
        for (int j = 0; j < 4; j++) {
            int idx = tid + j*256;
            int r = idx >> 6;
            float gxh = zs[idx];
            grads[idx] = (64.f*gxh - sg1[r] - xhs[idx]*sg2[r]) / (64.f*stds[r]);
        }
        // ---- M[r][j] = eta[j]*(Attn[r][j]+1) for j<=r ----
        {
            int r = tid >> 4, j = tid & 15;
            float m = 0.f;
            if (j <= r) {
                float d = 0.f;
#pragma unroll 8
                for (int k = 0; k < 64; k++) d += xqs[r*64+k] * xkTs[k*17+j];
                m = etas[j] * (d + 1.f);
            }
            Ms[tid] = m;
        }
        __syncthreads();

        // ---- Z1_bar = xq @ W1 + b1 - M @ grad ----
        {
            float bb = b1s[c];
            float a0=bb,a1=bb,a2=bb,a3=bb;
#pragma unroll 8
            for (int k = 0; k < 64; k++) {
                float w = W1s[k*64 + c];
                a0 += xqs[(r0+0)*64+k]*w;
                a1 += xqs[(r0+1)*64+k]*w;
                a2 += xqs[(r0+2)*64+k]*w;
                a3 += xqs[(r0+3)*64+k]*w;
            }
#pragma unroll
            for (int j = 0; j < 16; j++) {
                float g = grads[j*64 + c];
                a0 -= Ms[(r0+0)*16+j]*g;
                a1 -= Ms[(r0+1)*16+j]*g;
                a2 -= Ms[(r0+2)*16+j]*g;
                a3 -= Ms[(r0+3)*16+j]*g;
            }
            xhs[(r0+0)*64+c] = a0;
            xhs[(r0+1)*64+c] = a1;
            xhs[(r0+2)*64+c] = a2;
            xhs[(r0+3)*64+c] = a3;
        }
        __syncthreads();

        // ---- row stats of Z1_bar ----
        {
            int r = tid >> 4, i2 = tid & 15;
            float4 v = *(const float4*)&xhs[r*64 + i2*4];
            float s = v.x+v.y+v.z+v.w;
#pragma unroll
            for (int o = 8; o > 0; o >>= 1) s += __shfl_xor_sync(0xffffffffu, s, o);
            float mu = s * (1.f/64.f);
            float dx=v.x-mu, dy=v.y-mu, dz=v.z-mu, dw=v.w-mu;
            float ss = dx*dx+dy*dy+dz*dz+dw*dw;
#pragma unroll
            for (int o = 8; o > 0; o >>= 1) ss += __shfl_xor_sync(0xffffffffu, ss, o);
            if (i2 == 0) { mu2[r] = mu; std2[r] = sqrtf(ss*(1.f/64.f) + 1e-6f); }
        }
        __syncthreads();

        // ---- output write; exk = eta[r]*xk into zs ----
        for (int j = 0; j < 4; j++) {
            int idx = tid + j*256;
            int r = idx >> 6, cc = idx & 63;
            float z = xhs[idx];
            float o = xqs[idx] + (z - mu2[r])/std2[r]*lnw[cc] + lnb[cc];
            g_y[((size_t)b*Lc + n*Kc + r)*Dc + h*HDc + cc] = o;
            zs[idx] = etas[r] * xks[idx];
        }
        __syncthreads();

        // ---- state update ----
        {
            float greg[16];
#pragma unroll
            for (int j = 0; j < 16; j++) greg[j] = grads[j*64 + c];
            if (q4 == 0) {
                float s = 0.f;
#pragma unroll
                for (int j = 0; j < 16; j++) s += etas[j]*greg[j];
                b1s[c] -= s;
            }
#pragma unroll
            for (int kk = 0; kk < 16; kk++) {
                int k = q4*16 + kk;
                float s = 0.f;
#pragma unroll
                for (int j = 0; j < 16; j++) s += zs[j*64 + k] * greg[j];
                W1s[k*64 + c] -= s;
            }
        }
        __syncthreads();

        // ---- commit prefetched tile n+1 ----
        if (pf) {
#pragma unroll
            for (int j = 0; j < 4; j++) {
                int idx = tid + j*256;
                xqs[idx] = rq[j];
                xks[idx] = rk[j];
                xvs[idx] = rv[j];
                xkTs[(idx & 63)*17 + (idx >> 6)] = rk[j];
            }
            if (tid < 16) etas[tid] = re;
        }
        __syncthreads();
    }
}

// ---------------------------------------------------------------------------
// Post layernorm over D=2048 per token; emits fp16 hi directly.
// ---------------------------------------------------------------------------
__global__ __launch_bounds__(256) void postnorm_kernel(
    const float* __restrict__ pw, const float* __restrict__ pb)
{
    __shared__ float red[8];
    __shared__ float smu, svar;
    const int row = blockIdx.x, tid = threadIdx.x;
    const int lane = tid & 31, wid = tid >> 5;
    const float* x = g_y + (size_t)row*Dc;

    float v[8];
    *(float4*)(v)   = *(const float4*)&x[tid*8];
    *(float4*)(v+4) = *(const float4*)&x[tid*8+4];

    float s = v[0]+v[1]+v[2]+v[3]+v[4]+v[5]+v[6]+v[7];
#pragma unroll
    for (int o = 16; o > 0; o >>= 1) s += __shfl_xor_sync(0xffffffffu, s, o);
    if (lane == 0) red[wid] = s;
    __syncthreads();
    if (tid == 0) {
        float t = 0.f;
#pragma unroll
        for (int i = 0; i < 8; i++) t += red[i];
        smu = t * (1.f/2048.f);
    }
    __syncthreads();
    float mu = smu;

    float ss = 0.f;
#pragma unroll
    for (int i = 0; i < 8; i++) { float d = v[i]-mu; ss += d*d; }
#pragma unroll
    for (int o = 16; o > 0; o >>= 1) ss += __shfl_xor_sync(0xffffffffu, ss, o);
    if (lane == 0) red[wid] = ss;
    __syncthreads();
    if (tid == 0) {
        float t = 0.f;
#pragma unroll
        for (int i = 0; i < 8; i++) t += red[i];
        svar = t * (1.f/2048.f);
    }
    __syncthreads();
    float rstd = rsqrtf(svar + 1e-6f);

    __half hb[8];
#pragma unroll
    for (int i = 0; i < 8; i++) {
        int cc = tid*8 + i;
        float y = (v[i]-mu)*rstd*pw[cc] + pb[cc];
        hb[i] = __float2half_rn(y);
    }
    *(uint4*)&g_xnh[(size_t)row*Dc + tid*8] = *(uint4*)hb;
}

// ---------------------------------------------------------------------------
extern "C" void kernel_launch(void* const* d_in, const int* in_sizes, int n_in,
                              void* d_out, int out_size)
{
    (void)in_sizes; (void)n_in; (void)out_size;
    const float* hs    = (const float*)d_in[0];
    const float* wq_w  = (const float*)d_in[1];
    const float* wq_b  = (const float*)d_in[2];
    const float* wk_w  = (const float*)d_in[3];
    const float* wk_b  = (const float*)d_in[4];
    const float* wv_w  = (const float*)d_in[5];
    const float* wv_b  = (const float*)d_in[6];
    const float* wo_w  = (const float*)d_in[7];
    const float* wo_b  = (const float*)d_in[8];
    const float* tnw   = (const float*)d_in[9];
    const float* tnb   = (const float*)d_in[10];
    const float* lr_w  = (const float*)d_in[11];
    const float* lr_b  = (const float*)d_in[12];
    const float* W1    = (const float*)d_in[13];
    const float* b1    = (const float*)d_in[14];
    const float* pnw   = (const float*)d_in[15];
    const float* pnb   = (const float*)d_in[16];

    __half *ah, *wqh, *wql, *wkh, *wkl, *wvh, *wvl, *woh, *wol;
    cudaGetSymbolAddress((void**)&ah,  g_ah);
    cudaGetSymbolAddress((void**)&wqh, g_wqh);
    cudaGetSymbolAddress((void**)&wql, g_wql);
    cudaGetSymbolAddress((void**)&wkh, g_wkh);
    cudaGetSymbolAddress((void**)&wkl, g_wkl);
    cudaGetSymbolAddress((void**)&wvh, g_wvh);
    cudaGetSymbolAddress((void**)&wvl, g_wvl);
    cudaGetSymbolAddress((void**)&woh, g_woh);
    cudaGetSymbolAddress((void**)&wol, g_wol);

    cudaFuncSetAttribute(hgemm_kernel,
                         cudaFuncAttributeMaxDynamicSharedMemorySize, HG_SMEM);

    const int nA = Mrows*Dc;     // 16.7M
    const int nW = Dc*Dc;        // 4.2M
    conv_hi_kernel<<<nA/1024, 256>>>(hs, ah, nA);
    conv_hilo_kernel<<<nW/1024, 256>>>(wq_w, wqh, wql, nW);
    conv_hilo_kernel<<<nW/1024, 256>>>(wk_w, wkh, wkl, nW);
    conv_hilo_kernel<<<nW/1024, 256>>>(wv_w, wvh, wvl, nW);
    conv_hilo_kernel<<<nW/1024, 256>>>(wo_w, woh, wol, nW);

    // merged QKV GEMM: grid.x = 3 matrices x 16 col-tiles (weights via symbols)
    hgemm_kernel<<<dim3(48, 64), 256, HG_SMEM>>>(wq_b, wk_b, wv_b, nullptr, 1);
    lr_gemm_kernel<<<Mrows/64, 256>>>(hs, lr_w, lr_b);
    norm_kernel<<<(Bb*Hh*NMBc*Kc)/8, 256>>>(tnw, tnb);
    scan_kernel<<<Bb*Hh, 256>>>(W1, b1, tnw, tnb);
    postnorm_kernel<<<Mrows, 256>>>(pnw, pnb);
    hgemm_kernel<<<dim3(16, 64), 256, HG_SMEM>>>(wo_b, nullptr, nullptr,
                                                 (float*)d_out, 0);
}